// round 16
// baseline (speedup 1.0000x reference)
#include <cuda_runtime.h>
#include <math.h>

#define MAXF 200000
#define ACC_STRIDE 32   // floats per fragment record: 128B = one full L2 line

// Per-fragment accumulator: 16 used floats padded to a 128-byte stride so
// each fragment owns a private L2 line (no inter-fragment line contention
// in the REDG atomic path). Layout within the record:
//  0: sum fx   1: sum fy   2: sum fz   3: count
//  4: sum px   5: sum py   6: sum pz   7: sum (p x f).x
//  8: (pxf).y  9: (pxf).z 10: sum pxx 11: sum pyy
// 12: sum pzz 13: sum pxy 14: sum pxz 15: sum pyz   [16..31 unused padding]
// Zero-initialized at module load; frag_kernel restores zeros after each
// consume, so every graph replay sees a zeroed accumulator (self-cleaning).
__device__ __align__(128) float g_acc[ACC_STRIDE * MAXF];

__device__ __forceinline__ void red_v4(float* addr, float a, float b, float c, float d) {
    asm volatile("red.global.add.v4.f32 [%0], {%1,%2,%3,%4};"
                 :: "l"(addr), "f"(a), "f"(b), "f"(c), "f"(d) : "memory");
}

__global__ void scatter_kernel(const float* __restrict__ f_atom,
                               const float* __restrict__ atom_pos,
                               const int*   __restrict__ frag_id,
                               int N) {
    int i = blockIdx.x * blockDim.x + threadIdx.x;
    if (i >= N) return;

    // Streaming loads (evict-first): inputs are read exactly once per replay;
    // keep them from evicting the L2-resident accumulator that REDG targets.
    int fid = __ldcs(&frag_id[i]);

    float fx = __ldcs(&f_atom[3 * i + 0]);
    float fy = __ldcs(&f_atom[3 * i + 1]);
    float fz = __ldcs(&f_atom[3 * i + 2]);
    float px = __ldcs(&atom_pos[3 * i + 0]);
    float py = __ldcs(&atom_pos[3 * i + 1]);
    float pz = __ldcs(&atom_pos[3 * i + 2]);

    float* base = g_acc + (size_t)fid * ACC_STRIDE;

    // First message depends only on raw loads — issue before computing
    // products so the REDG stream starts while FMA fills the rest.
    red_v4(base + 0, fx, fy, fz, 1.0f);

    // p x f
    float cx = py * fz - pz * fy;
    float cy = pz * fx - px * fz;
    float cz = px * fy - py * fx;

    red_v4(base +  4, px, py, pz, cx);
    red_v4(base +  8, cy, cz, px * px, py * py);
    red_v4(base + 12, pz * pz, px * py, px * pz, py * pz);
}

// Branchless Jacobi for symmetric 3x3: 3 fixed sweeps (9 rotations) — the
// measured minimum (2 sweeps breaks omega at 1.8e-3 rel_err; 3 gives 5e-7).
// Sweep loop kept rolled (schedules better than full unroll, R7 vs R8).
// 2 rsqrt per rotation (half-angle form, no divisions).
// A destroyed to diagonal; V holds eigenvectors as COLUMNS (A = V D V^T).
// Degenerate u=v=0 guarded by bias -> identity rotation.
__device__ __forceinline__ void jacobi3(float A[3][3], float V[3][3]) {
    V[0][0] = 1.f; V[0][1] = 0.f; V[0][2] = 0.f;
    V[1][0] = 0.f; V[1][1] = 1.f; V[1][2] = 0.f;
    V[2][0] = 0.f; V[2][1] = 0.f; V[2][2] = 1.f;

    #pragma unroll 1
    for (int sweep = 0; sweep < 3; sweep++) {
        #pragma unroll
        for (int k = 0; k < 3; k++) {
            const int p = (k == 2) ? 1 : 0;
            const int q = (k == 0) ? 1 : 2;
            const int r = 3 - p - q;

            float apq = A[p][q];
            float u = A[q][q] - A[p][p];
            u = u + copysignf(1e-35f, u);        // u=v=0 -> identity rot
            float v = 2.0f * apq;

            float rinv = rsqrtf(u * u + v * v);  // MUFU 1
            float cos2 = fabsf(u) * rinv;        // in [0,1]
            float c2 = 0.5f * (1.0f + cos2);     // cos^2(phi) >= 0.5
            float cinv = rsqrtf(c2);             // MUFU 2
            float c = c2 * cinv;                 // cos(phi)
            float s = 0.5f * v * copysignf(rinv, u) * cinv;  // sin(phi)

            float s2 = s * s;
            float sc2 = 2.0f * s * c;

            float app = A[p][p];
            float aqq = A[q][q];
            float napp = c2 * app + s2 * aqq - sc2 * apq;
            float naqq = s2 * app + c2 * aqq + sc2 * apq;

            float arp = A[r][p];
            float arq = A[r][q];
            float nrp = c * arp - s * arq;
            float nrq = s * arp + c * arq;

            A[p][p] = napp;
            A[q][q] = naqq;
            A[p][q] = 0.f; A[q][p] = 0.f;
            A[r][p] = nrp; A[p][r] = nrp;
            A[r][q] = nrq; A[q][r] = nrq;

            #pragma unroll
            for (int i = 0; i < 3; i++) {
                float vip = V[i][p];
                float viq = V[i][q];
                V[i][p] = c * vip - s * viq;
                V[i][q] = s * vip + c * viq;
            }
        }
    }
}

__global__ void __launch_bounds__(128) frag_kernel(
        const float* __restrict__ T_frag,
        const int*   __restrict__ frag_sizes,
        float* __restrict__ out, int F) {
    int f = blockIdx.x * blockDim.x + threadIdx.x;
    if (f >= F) return;

    float4* acc4 = reinterpret_cast<float4*>(g_acc) + (size_t)f * (ACC_STRIDE / 4);
    float4 a0 = acc4[0];
    float4 a1 = acc4[1];
    float4 a2 = acc4[2];
    float4 a3 = acc4[3];

    // Self-clean for the next graph replay (stream order guarantees the
    // next scatter starts after this kernel finishes). Only the used 64B.
    float4 z = make_float4(0.f, 0.f, 0.f, 0.f);
    acc4[0] = z; acc4[1] = z; acc4[2] = z; acc4[3] = z;

    float sfx = a0.x, sfy = a0.y, sfz = a0.z, n = a0.w;
    float spx = a1.x, spy = a1.y, spz = a1.z;
    float crx = a1.w, cry = a2.x, crz = a2.y;
    float sxx = a2.z, syy = a2.w, szz = a3.x;
    float sxy = a3.y, sxz = a3.z, syz = a3.w;

    float Tx = T_frag[3 * f + 0];
    float Ty = T_frag[3 * f + 1];
    float Tz = T_frag[3 * f + 2];

    float dinv = __fdividef(1.0f, fmaxf(n, 1.0f));
    float vx = sfx * dinv, vy = sfy * dinv, vz = sfz * dinv;

    // torque = sum(p x f) - T x (sum f)
    float tx = crx - (Ty * sfz - Tz * sfy);
    float ty = cry - (Tz * sfx - Tx * sfz);
    float tz = crz - (Tx * sfy - Ty * sfx);

    // Centered second moments
    float Sxx = sxx - 2.f * Tx * spx + n * Tx * Tx;
    float Syy = syy - 2.f * Ty * spy + n * Ty * Ty;
    float Szz = szz - 2.f * Tz * spz + n * Tz * Tz;
    float Sxy = sxy - Tx * spy - Ty * spx + n * Tx * Ty;
    float Sxz = sxz - Tx * spz - Tz * spx + n * Tx * Tz;
    float Syz = syz - Ty * spz - Tz * spy + n * Ty * Tz;

    // I = tr(S) * eye - S
    float A[3][3];
    A[0][0] = Syy + Szz;  A[1][1] = Sxx + Szz;  A[2][2] = Sxx + Syy;
    A[0][1] = -Sxy; A[1][0] = -Sxy;
    A[0][2] = -Sxz; A[2][0] = -Sxz;
    A[1][2] = -Syz; A[2][1] = -Syz;

    float V[3][3];
    jacobi3(A, V);
    float w[3] = {A[0][0], A[1][1], A[2][2]};

    float maxe = fmaxf(fmaxf(w[0], w[1]), w[2]);
    maxe = fmaxf(maxe, 1e-8f);

    int fs = frag_sizes[f];
    float gate = (fs <= 1) ? 0.0f : 1.0f;
    float obs[3];
    #pragma unroll
    for (int i = 0; i < 3; i++)
        obs[i] = (w[i] > 0.01f * maxe) ? gate : 0.0f;

    float coef[3];
    #pragma unroll
    for (int i = 0; i < 3; i++) {
        float te = V[0][i] * tx + V[1][i] * ty + V[2][i] * tz;
        coef[i] = __fdividef(te, fmaxf(w[i], 1e-6f)) * obs[i];
    }

    float om[3];
    #pragma unroll
    for (int j = 0; j < 3; j++)
        om[j] = V[j][0] * coef[0] + V[j][1] * coef[1] + V[j][2] * coef[2];

    out[3 * f + 0] = vx;
    out[3 * f + 1] = vy;
    out[3 * f + 2] = vz;

    float* o_om = out + 3 * F;
    o_om[3 * f + 0] = om[0];
    o_om[3 * f + 1] = om[1];
    o_om[3 * f + 2] = om[2];

    float* o_P = out + 6 * F;
    #pragma unroll
    for (int j = 0; j < 3; j++)
        #pragma unroll
        for (int k2 = 0; k2 < 3; k2++) {
            float pv = V[j][0] * obs[0] * V[k2][0]
                     + V[j][1] * obs[1] * V[k2][1]
                     + V[j][2] * obs[2] * V[k2][2];
            o_P[9 * f + 3 * j + k2] = pv;
        }
}

extern "C" void kernel_launch(void* const* d_in, const int* in_sizes, int n_in,
                              void* d_out, int out_size) {
    const float* f_atom     = (const float*)d_in[0];
    const float* atom_pos   = (const float*)d_in[1];
    const float* T_frag     = (const float*)d_in[2];
    const int*   frag_id    = (const int*)d_in[3];
    const int*   frag_sizes = (const int*)d_in[4];

    int N = in_sizes[0] / 3;
    int F = in_sizes[2] / 3;

    float* out = (float*)d_out;

    scatter_kernel<<<(N + 255) / 256, 256>>>(f_atom, atom_pos, frag_id, N);
    frag_kernel<<<(F + 127) / 128, 128>>>(T_frag, frag_sizes, out, F);
}

// round 17
// speedup vs baseline: 1.0580x; 1.0580x over previous
#include <cuda_runtime.h>
#include <math.h>

#define MAXF 200000

// Per-fragment accumulator: 16 floats, 64B-aligned.
//  0: sum fx   1: sum fy   2: sum fz   3: count
//  4: sum px   5: sum py   6: sum pz   7: sum (p x f).x
//  8: (pxf).y  9: (pxf).z 10: sum pxx 11: sum pyy
// 12: sum pzz 13: sum pxy 14: sum pxz 15: sum pyz
// Zero-initialized at module load; frag_kernel restores zeros after each
// consume, so every graph replay sees a zeroed accumulator (self-cleaning).
// 16 f32 scalars = 4 x red.v4 messages/atom: the PTX minimum (red .f32 is
// capped at .v4/128-bit) and the information minimum for this decomposition.
// 64B stride measured strictly better than 128B-padded (R15 vs R16).
__device__ __align__(64) float g_acc[16 * MAXF];

__device__ __forceinline__ void red_v4(float* addr, float a, float b, float c, float d) {
    asm volatile("red.global.add.v4.f32 [%0], {%1,%2,%3,%4};"
                 :: "l"(addr), "f"(a), "f"(b), "f"(c), "f"(d) : "memory");
}

__global__ void scatter_kernel(const float* __restrict__ f_atom,
                               const float* __restrict__ atom_pos,
                               const int*   __restrict__ frag_id,
                               int N) {
    int i = blockIdx.x * blockDim.x + threadIdx.x;
    if (i >= N) return;

    // Streaming loads (evict-first): inputs are read exactly once per replay;
    // keep them from evicting the L2-resident accumulator that REDG targets.
    int fid = __ldcs(&frag_id[i]);

    float fx = __ldcs(&f_atom[3 * i + 0]);
    float fy = __ldcs(&f_atom[3 * i + 1]);
    float fz = __ldcs(&f_atom[3 * i + 2]);
    float px = __ldcs(&atom_pos[3 * i + 0]);
    float py = __ldcs(&atom_pos[3 * i + 1]);
    float pz = __ldcs(&atom_pos[3 * i + 2]);

    float* base = g_acc + (size_t)fid * 16;

    // First message depends only on raw loads — issue before computing
    // products so the REDG stream starts while FMA fills the rest.
    red_v4(base + 0, fx, fy, fz, 1.0f);

    // p x f
    float cx = py * fz - pz * fy;
    float cy = pz * fx - px * fz;
    float cz = px * fy - py * fx;

    red_v4(base +  4, px, py, pz, cx);
    red_v4(base +  8, cy, cz, px * px, py * py);
    red_v4(base + 12, pz * pz, px * py, px * pz, py * pz);
}

// Branchless Jacobi for symmetric 3x3: 3 fixed sweeps (9 rotations) — the
// measured minimum (2 sweeps breaks omega at 1.8e-3 rel_err; 3 gives 5e-7).
// Sweep loop kept rolled (schedules better than full unroll, R7 vs R8).
// 2 rsqrt per rotation (half-angle form, no divisions).
// A destroyed to diagonal; V holds eigenvectors as COLUMNS (A = V D V^T).
// Degenerate u=v=0 guarded by bias -> identity rotation.
__device__ __forceinline__ void jacobi3(float A[3][3], float V[3][3]) {
    V[0][0] = 1.f; V[0][1] = 0.f; V[0][2] = 0.f;
    V[1][0] = 0.f; V[1][1] = 1.f; V[1][2] = 0.f;
    V[2][0] = 0.f; V[2][1] = 0.f; V[2][2] = 1.f;

    #pragma unroll 1
    for (int sweep = 0; sweep < 3; sweep++) {
        #pragma unroll
        for (int k = 0; k < 3; k++) {
            const int p = (k == 2) ? 1 : 0;
            const int q = (k == 0) ? 1 : 2;
            const int r = 3 - p - q;

            float apq = A[p][q];
            float u = A[q][q] - A[p][p];
            u = u + copysignf(1e-35f, u);        // u=v=0 -> identity rot
            float v = 2.0f * apq;

            float rinv = rsqrtf(u * u + v * v);  // MUFU 1
            float cos2 = fabsf(u) * rinv;        // in [0,1]
            float c2 = 0.5f * (1.0f + cos2);     // cos^2(phi) >= 0.5
            float cinv = rsqrtf(c2);             // MUFU 2
            float c = c2 * cinv;                 // cos(phi)
            float s = 0.5f * v * copysignf(rinv, u) * cinv;  // sin(phi)

            float s2 = s * s;
            float sc2 = 2.0f * s * c;

            float app = A[p][p];
            float aqq = A[q][q];
            float napp = c2 * app + s2 * aqq - sc2 * apq;
            float naqq = s2 * app + c2 * aqq + sc2 * apq;

            float arp = A[r][p];
            float arq = A[r][q];
            float nrp = c * arp - s * arq;
            float nrq = s * arp + c * arq;

            A[p][p] = napp;
            A[q][q] = naqq;
            A[p][q] = 0.f; A[q][p] = 0.f;
            A[r][p] = nrp; A[p][r] = nrp;
            A[r][q] = nrq; A[q][r] = nrq;

            #pragma unroll
            for (int i = 0; i < 3; i++) {
                float vip = V[i][p];
                float viq = V[i][q];
                V[i][p] = c * vip - s * viq;
                V[i][q] = s * vip + c * viq;
            }
        }
    }
}

__global__ void __launch_bounds__(128) frag_kernel(
        const float* __restrict__ T_frag,
        const int*   __restrict__ frag_sizes,
        float* __restrict__ out, int F) {
    int f = blockIdx.x * blockDim.x + threadIdx.x;
    if (f >= F) return;

    float4* acc4 = reinterpret_cast<float4*>(g_acc) + (size_t)f * 4;
    float4 a0 = acc4[0];
    float4 a1 = acc4[1];
    float4 a2 = acc4[2];
    float4 a3 = acc4[3];

    // Self-clean for the next graph replay (stream order guarantees the
    // next scatter starts after this kernel finishes).
    float4 z = make_float4(0.f, 0.f, 0.f, 0.f);
    acc4[0] = z; acc4[1] = z; acc4[2] = z; acc4[3] = z;

    float sfx = a0.x, sfy = a0.y, sfz = a0.z, n = a0.w;
    float spx = a1.x, spy = a1.y, spz = a1.z;
    float crx = a1.w, cry = a2.x, crz = a2.y;
    float sxx = a2.z, syy = a2.w, szz = a3.x;
    float sxy = a3.y, sxz = a3.z, syz = a3.w;

    float Tx = T_frag[3 * f + 0];
    float Ty = T_frag[3 * f + 1];
    float Tz = T_frag[3 * f + 2];

    float dinv = __fdividef(1.0f, fmaxf(n, 1.0f));
    float vx = sfx * dinv, vy = sfy * dinv, vz = sfz * dinv;

    // torque = sum(p x f) - T x (sum f)
    float tx = crx - (Ty * sfz - Tz * sfy);
    float ty = cry - (Tz * sfx - Tx * sfz);
    float tz = crz - (Tx * sfy - Ty * sfx);

    // Centered second moments
    float Sxx = sxx - 2.f * Tx * spx + n * Tx * Tx;
    float Syy = syy - 2.f * Ty * spy + n * Ty * Ty;
    float Szz = szz - 2.f * Tz * spz + n * Tz * Tz;
    float Sxy = sxy - Tx * spy - Ty * spx + n * Tx * Ty;
    float Sxz = sxz - Tx * spz - Tz * spx + n * Tx * Tz;
    float Syz = syz - Ty * spz - Tz * spy + n * Ty * Tz;

    // I = tr(S) * eye - S
    float A[3][3];
    A[0][0] = Syy + Szz;  A[1][1] = Sxx + Szz;  A[2][2] = Sxx + Syy;
    A[0][1] = -Sxy; A[1][0] = -Sxy;
    A[0][2] = -Sxz; A[2][0] = -Sxz;
    A[1][2] = -Syz; A[2][1] = -Syz;

    float V[3][3];
    jacobi3(A, V);
    float w[3] = {A[0][0], A[1][1], A[2][2]};

    float maxe = fmaxf(fmaxf(w[0], w[1]), w[2]);
    maxe = fmaxf(maxe, 1e-8f);

    int fs = frag_sizes[f];
    float gate = (fs <= 1) ? 0.0f : 1.0f;
    float obs[3];
    #pragma unroll
    for (int i = 0; i < 3; i++)
        obs[i] = (w[i] > 0.01f * maxe) ? gate : 0.0f;

    float coef[3];
    #pragma unroll
    for (int i = 0; i < 3; i++) {
        float te = V[0][i] * tx + V[1][i] * ty + V[2][i] * tz;
        coef[i] = __fdividef(te, fmaxf(w[i], 1e-6f)) * obs[i];
    }

    float om[3];
    #pragma unroll
    for (int j = 0; j < 3; j++)
        om[j] = V[j][0] * coef[0] + V[j][1] * coef[1] + V[j][2] * coef[2];

    out[3 * f + 0] = vx;
    out[3 * f + 1] = vy;
    out[3 * f + 2] = vz;

    float* o_om = out + 3 * F;
    o_om[3 * f + 0] = om[0];
    o_om[3 * f + 1] = om[1];
    o_om[3 * f + 2] = om[2];

    float* o_P = out + 6 * F;
    #pragma unroll
    for (int j = 0; j < 3; j++)
        #pragma unroll
        for (int k2 = 0; k2 < 3; k2++) {
            float pv = V[j][0] * obs[0] * V[k2][0]
                     + V[j][1] * obs[1] * V[k2][1]
                     + V[j][2] * obs[2] * V[k2][2];
            o_P[9 * f + 3 * j + k2] = pv;
        }
}

extern "C" void kernel_launch(void* const* d_in, const int* in_sizes, int n_in,
                              void* d_out, int out_size) {
    const float* f_atom     = (const float*)d_in[0];
    const float* atom_pos   = (const float*)d_in[1];
    const float* T_frag     = (const float*)d_in[2];
    const int*   frag_id    = (const int*)d_in[3];
    const int*   frag_sizes = (const int*)d_in[4];

    int N = in_sizes[0] / 3;
    int F = in_sizes[2] / 3;

    float* out = (float*)d_out;

    scatter_kernel<<<(N + 255) / 256, 256>>>(f_atom, atom_pos, frag_id, N);
    frag_kernel<<<(F + 127) / 128, 128>>>(T_frag, frag_sizes, out, F);
}